// round 1
// baseline (speedup 1.0000x reference)
#include <cuda_runtime.h>
#include <cuda_bf16.h>

// SparseAttention (entmax-1.5) fused kernel for GB300 sm_103a.
// Phase 1: bf16 mma.sync QK^T per 128x128 tile; track row max; collect
//          candidate (score,col) pairs with score > rowmax - 3.5 (superset of
//          true entmax support {z > z_max - 1} given worst-case bf16 error <0.35).
// Phase 2: sort candidates (determinism), refine scores in exact fp32,
//          100-iter bisection exactly mirroring the reference, sparse P@V.

#define BATCH 8
#define SEQ   2048
#define DIM   128
#define BM    128              // query rows per CTA
#define BN    128              // key cols per tile
#define NT    (SEQ / BN)       // 16 key tiles
#define QT    (SEQ / BM)       // 16 query tiles
#define CAP   64               // candidate capacity per row
#define CSTR  65               // padded stride (bank-conflict-free lane-per-row)
#define QSTR  136              // bf16 row stride (128 + 8 pad -> conflict-free ldmatrix)
#define NITER 100

// ---- smem layout (bytes) ----
#define OFF_QHI  0
#define OFF_KHI  (OFF_QHI + BM * QSTR * 2)            // 34816
#define OFF_CS   (OFF_KHI + BN * QSTR * 2)            // 69632
#define OFF_CC   (OFF_CS + BM * CSTR * 4)             // 102912
#define OFF_RM   (OFF_CC + BM * CSTR * 4)             // 136192
#define OFF_CNT  (OFF_RM + BM * 4)                    // 136704
#define OFF_TAU  (OFF_CNT + BM * 4)                   // 137216
#define OFF_Z    (OFF_TAU + BM * 4)                   // 137728
#define SMEM_BYTES (OFF_Z + BM * 4)                   // 138240

// order-preserving float<->uint encoding for atomicMax on shared memory
static __device__ __forceinline__ unsigned fenc(float f) {
    unsigned u = __float_as_uint(f);
    return (u & 0x80000000u) ? ~u : (u | 0x80000000u);
}
static __device__ __forceinline__ float fdec(unsigned e) {
    return (e & 0x80000000u) ? __uint_as_float(e & 0x7fffffffu)
                             : __uint_as_float(~e);
}

static __device__ __forceinline__ void ldsm4(unsigned* r, unsigned addr) {
    asm volatile("ldmatrix.sync.aligned.m8n8.x4.shared.b16 {%0,%1,%2,%3}, [%4];\n"
                 : "=r"(r[0]), "=r"(r[1]), "=r"(r[2]), "=r"(r[3])
                 : "r"(addr) : "memory");
}
static __device__ __forceinline__ void ldsm2(unsigned* r, unsigned addr) {
    asm volatile("ldmatrix.sync.aligned.m8n8.x2.shared.b16 {%0,%1}, [%2];\n"
                 : "=r"(r[0]), "=r"(r[1])
                 : "r"(addr) : "memory");
}
static __device__ __forceinline__ void mma16816(float* c, const unsigned* a, const unsigned* b) {
    asm volatile("mma.sync.aligned.m16n8k16.row.col.f32.bf16.bf16.f32 "
                 "{%0,%1,%2,%3}, {%4,%5,%6,%7}, {%8,%9}, {%0,%1,%2,%3};\n"
                 : "+f"(c[0]), "+f"(c[1]), "+f"(c[2]), "+f"(c[3])
                 : "r"(a[0]), "r"(a[1]), "r"(a[2]), "r"(a[3]),
                   "r"(b[0]), "r"(b[1]));
}

__global__ __launch_bounds__(256, 1)
void entmax_attn_kernel(const float* __restrict__ Q, const float* __restrict__ K,
                        const float* __restrict__ V, float* __restrict__ O)
{
    extern __shared__ unsigned char smem[];
    __nv_bfloat16* Qhi   = (__nv_bfloat16*)(smem + OFF_QHI);
    __nv_bfloat16* Khi   = (__nv_bfloat16*)(smem + OFF_KHI);
    float*         candS = (float*)(smem + OFF_CS);
    int*           candC = (int*)(smem + OFF_CC);
    unsigned*      rowM  = (unsigned*)(smem + OFF_RM);
    int*           cnt   = (int*)(smem + OFF_CNT);
    float*         tauA  = (float*)(smem + OFF_TAU);
    float*         zA    = (float*)(smem + OFF_Z);

    const int tid  = threadIdx.x;
    const int lane = tid & 31;
    const int wid  = tid >> 5;
    const int b    = blockIdx.y;
    const int qt   = blockIdx.x;
    const int q0   = qt * BM;

    const float* Qb = Q + ((size_t)b * SEQ + q0) * DIM;
    const float* Kb = K + (size_t)b * SEQ * DIM;
    const float* Vb = V + (size_t)b * SEQ * DIM;

    // warp tiling: 2 warps in M (64 rows each), 4 warps in N (32 cols each)
    const int wm = wid & 1;
    const int wn = wid >> 1;
    const int g  = lane >> 2;   // groupID
    const int t  = lane & 3;    // threadInGroup

    // ldmatrix per-lane address components
    const int aRow = (lane & 7) + ((lane >> 3) & 1) * 8;  // A x4
    const int aK   = ((lane >> 4) & 1) * 8;
    const int bRow = lane & 7;                            // B x2 (lanes>=16 replicate, ignored)
    const int bK   = ((lane >> 3) & 1) * 8;

    if (tid < BM) { rowM[tid] = 0u; cnt[tid] = 0; }

    // load Q tile once: fp32 -> bf16
    for (int i = tid; i < BM * (DIM / 2); i += 256) {
        int r = i >> 6, cp = i & 63;
        float2 v = *(const float2*)(Qb + r * DIM + cp * 2);
        __nv_bfloat162 h;
        h.x = __float2bfloat16(v.x);
        h.y = __float2bfloat16(v.y);
        *(__nv_bfloat162*)(Qhi + r * QSTR + cp * 2) = h;
    }

    const unsigned qS = (unsigned)__cvta_generic_to_shared(Qhi);
    const unsigned kS = (unsigned)__cvta_generic_to_shared(Khi);

    for (int nt = 0; nt < NT; nt++) {
        __syncthreads();   // Q/K smem + prior collection done
        const float* Kt = Kb + (size_t)nt * BN * DIM;
        for (int i = tid; i < BN * (DIM / 2); i += 256) {
            int r = i >> 6, cp = i & 63;
            float2 v = *(const float2*)(Kt + r * DIM + cp * 2);
            __nv_bfloat162 h;
            h.x = __float2bfloat16(v.x);
            h.y = __float2bfloat16(v.y);
            *(__nv_bfloat162*)(Khi + r * QSTR + cp * 2) = h;
        }
        __syncthreads();

        float acc[4][4][4];
        #pragma unroll
        for (int m = 0; m < 4; m++)
            #pragma unroll
            for (int n = 0; n < 4; n++)
                #pragma unroll
                for (int e = 0; e < 4; e++) acc[m][n][e] = 0.f;

        #pragma unroll
        for (int ks = 0; ks < 8; ks++) {
            unsigned a[4][4], bb[4][2];
            #pragma unroll
            for (int m = 0; m < 4; m++) {
                unsigned off = (unsigned)(((wm * 64 + m * 16 + aRow) * QSTR + ks * 16 + aK) * 2);
                ldsm4(a[m], qS + off);
            }
            #pragma unroll
            for (int n = 0; n < 4; n++) {
                unsigned off = (unsigned)(((wn * 32 + n * 8 + bRow) * QSTR + ks * 16 + bK) * 2);
                ldsm2(bb[n], kS + off);
            }
            #pragma unroll
            for (int m = 0; m < 4; m++)
                #pragma unroll
                for (int n = 0; n < 4; n++)
                    mma16816(acc[m][n], a[m], bb[n]);
        }

        // per-row running max (encoded atomicMax over quads)
        #pragma unroll
        for (int m = 0; m < 4; m++) {
            #pragma unroll
            for (int h = 0; h < 2; h++) {
                float lm = -3.0e38f;
                #pragma unroll
                for (int n = 0; n < 4; n++)
                    lm = fmaxf(lm, fmaxf(acc[m][n][h * 2], acc[m][n][h * 2 + 1]));
                lm = fmaxf(lm, __shfl_xor_sync(0xffffffffu, lm, 1));
                lm = fmaxf(lm, __shfl_xor_sync(0xffffffffu, lm, 2));
                if ((lane & 3) == 0)
                    atomicMax(&rowM[wm * 64 + m * 16 + h * 8 + g], fenc(lm));
            }
        }
        __syncthreads();

        // collect candidates: score > running_rowmax - 3.5
        #pragma unroll
        for (int m = 0; m < 4; m++) {
            #pragma unroll
            for (int h = 0; h < 2; h++) {
                const int r = wm * 64 + m * 16 + h * 8 + g;
                const float thr = fdec(rowM[r]) - 3.5f;
                #pragma unroll
                for (int n = 0; n < 4; n++) {
                    #pragma unroll
                    for (int e = 0; e < 2; e++) {
                        float s = acc[m][n][h * 2 + e];
                        if (s > thr) {
                            int p = atomicAdd(&cnt[r], 1);
                            if (p < CAP) {
                                candS[r * CSTR + p] = s;
                                candC[r * CSTR + p] = nt * BN + wn * 32 + n * 8 + t * 2 + e;
                            }
                        }
                    }
                }
            }
        }
    }
    __syncthreads();

    // ---- sort + exact fp32 rescore + bisection (lane-per-row, warps 0-3) ----
    if (wid < 4) {
        const int r = wid * 32 + lane;
        int c_ = cnt[r]; if (c_ > CAP) c_ = CAP;
        float* cs = candS + r * CSTR;
        int*   cc = candC + r * CSTR;

        // deterministic order: insertion sort by column index
        for (int i = 1; i < c_; i++) {
            float sv = cs[i]; int kv = cc[i]; int j = i - 1;
            while (j >= 0 && cc[j] > kv) { cc[j + 1] = cc[j]; cs[j + 1] = cs[j]; j--; }
            cc[j + 1] = kv; cs[j + 1] = sv;
        }

        // exact fp32 rescore of candidates (removes all bf16 error)
        const float* qp = Qb + r * DIM;
        float smax = -3.0e38f;
        for (int j = 0; j < c_; j++) {
            const float* kp = Kb + (size_t)cc[j] * DIM;
            float s0 = 0.f, s1 = 0.f, s2 = 0.f, s3 = 0.f;
            #pragma unroll
            for (int d = 0; d < DIM / 4; d++) {
                float4 qv = *(const float4*)(qp + d * 4);
                float4 kv = *(const float4*)(kp + d * 4);
                s0 = fmaf(qv.x, kv.x, s0);
                s1 = fmaf(qv.y, kv.y, s1);
                s2 = fmaf(qv.z, kv.z, s2);
                s3 = fmaf(qv.w, kv.w, s3);
            }
            float s = (s0 + s1) + (s2 + s3);
            cs[j] = s;
            smax = fmaxf(smax, s);
        }

        // bisection (faithful to the reference; z = 0.5*s is exact in fp32)
        const float zmax = 0.5f * smax;
        float tmin = zmax - 1.0f;
        float tmax = zmax - 0.022097086912079608f;   // float32(2048^-0.5)
        float tau = 0.5f * (tmin + tmax), Zv = 0.f;
        for (int it = 0; it < NITER; it++) {
            tau = 0.5f * (tmin + tmax);
            Zv = 0.f;
            for (int j = 0; j < c_; j++) {
                float dz = fmaxf(0.5f * cs[j] - tau, 0.f);
                Zv += dz * dz;
            }
            if (Zv >= 1.0f) tmin = tau; else tmax = tau;
        }
        tauA[r] = tau;
        zA[r]   = Zv;
    }
    __syncthreads();

    // ---- sparse P@V: warp per row group, float4 coalesced V gather ----
    for (int rr = 0; rr < 16; rr++) {
        const int r = wid * 16 + rr;
        int c_ = cnt[r]; if (c_ > CAP) c_ = CAP;
        const float tau = tauA[r];
        const float Zv  = zA[r];
        float ax = 0.f, ay = 0.f, az = 0.f, aw = 0.f;
        for (int j = 0; j < c_; j++) {
            float dz = fmaxf(0.5f * candS[r * CSTR + j] - tau, 0.f);
            float w = (dz * dz) / Zv;
            const float4 v = *(const float4*)(Vb + (size_t)candC[r * CSTR + j] * DIM + lane * 4);
            ax = fmaf(w, v.x, ax);
            ay = fmaf(w, v.y, ay);
            az = fmaf(w, v.z, az);
            aw = fmaf(w, v.w, aw);
        }
        *(float4*)(O + ((size_t)b * SEQ + q0 + r) * DIM + lane * 4) = make_float4(ax, ay, az, aw);
    }
}

extern "C" void kernel_launch(void* const* d_in, const int* in_sizes, int n_in,
                              void* d_out, int out_size) {
    const float* Q = (const float*)d_in[0];
    const float* K = (const float*)d_in[1];
    const float* V = (const float*)d_in[2];
    float* O = (float*)d_out;

    cudaFuncSetAttribute(entmax_attn_kernel,
                         cudaFuncAttributeMaxDynamicSharedMemorySize, SMEM_BYTES);
    dim3 grid(QT, BATCH);
    entmax_attn_kernel<<<grid, 256, SMEM_BYTES>>>(Q, K, V, O);
}

// round 2
// speedup vs baseline: 1.0793x; 1.0793x over previous
#include <cuda_runtime.h>
#include <cuda_bf16.h>

// SparseAttention (entmax-1.5) fused kernel for GB300 sm_103a. Round 2:
//  - prologue kernel pre-converts Q,K to bf16 in __device__ scratch (once, not per-CTA)
//  - 3-stage cp.async double-buffered K-tile pipeline hides gmem latency behind MMA
//  - same candidate-collect + exact-fp32-refine + 100-iter bisection tail.

#define BATCH 8
#define SEQ   2048
#define DIM   128
#define BM    128
#define BN    128
#define NT    (SEQ / BN)
#define QT    (SEQ / BM)
#define CAP   64
#define CSTR  65
#define QSTR  136              // bf16 row stride (128+8 pad), 272B: 16B-aligned, ldsm conflict-free
#define NITER 100
#define STAGES 3

#define TILE_B  (BM * QSTR * 2)                       // 34816 bytes per bf16 tile
// ---- smem layout (bytes) ----
#define OFF_QHI  0
#define OFF_KHI  (OFF_QHI + TILE_B)
#define OFF_CS   (OFF_KHI + STAGES * TILE_B)          // 139264
#define OFF_CC   (OFF_CS + BM * CSTR * 4)
#define OFF_RM   (OFF_CC + BM * CSTR * 4)
#define OFF_CNT  (OFF_RM + BM * 4)
#define OFF_TAU  (OFF_CNT + BM * 4)
#define OFF_Z    (OFF_TAU + BM * 4)
#define SMEM_BYTES (OFF_Z + BM * 4)                   // 207872

__device__ __nv_bfloat16 g_Qh[BATCH * SEQ * DIM];
__device__ __nv_bfloat16 g_Kh[BATCH * SEQ * DIM];

// ---------------- prologue: fp32 -> bf16 conversion ----------------
__global__ void cvt_kernel(const float* __restrict__ Q, const float* __restrict__ K) {
    size_t i = ((size_t)blockIdx.x * blockDim.x + threadIdx.x) * 4;
    float4 q = *(const float4*)(Q + i);
    float4 k = *(const float4*)(K + i);
    __nv_bfloat162 q0, q1, k0, k1;
    q0.x = __float2bfloat16(q.x); q0.y = __float2bfloat16(q.y);
    q1.x = __float2bfloat16(q.z); q1.y = __float2bfloat16(q.w);
    k0.x = __float2bfloat16(k.x); k0.y = __float2bfloat16(k.y);
    k1.x = __float2bfloat16(k.z); k1.y = __float2bfloat16(k.w);
    *(__nv_bfloat162*)(g_Qh + i)     = q0;
    *(__nv_bfloat162*)(g_Qh + i + 2) = q1;
    *(__nv_bfloat162*)(g_Kh + i)     = k0;
    *(__nv_bfloat162*)(g_Kh + i + 2) = k1;
}

// ---------------- helpers ----------------
static __device__ __forceinline__ unsigned fenc(float f) {
    unsigned u = __float_as_uint(f);
    return (u & 0x80000000u) ? ~u : (u | 0x80000000u);
}
static __device__ __forceinline__ float fdec(unsigned e) {
    return (e & 0x80000000u) ? __uint_as_float(e & 0x7fffffffu)
                             : __uint_as_float(~e);
}
static __device__ __forceinline__ void cpasync16(unsigned dst, const void* src) {
    asm volatile("cp.async.cg.shared.global [%0], [%1], 16;\n" :: "r"(dst), "l"(src));
}
static __device__ __forceinline__ void cp_commit() {
    asm volatile("cp.async.commit_group;\n");
}
template <int N>
static __device__ __forceinline__ void cp_wait() {
    asm volatile("cp.async.wait_group %0;\n" :: "n"(N));
}
static __device__ __forceinline__ void ldsm4(unsigned* r, unsigned addr) {
    asm volatile("ldmatrix.sync.aligned.m8n8.x4.shared.b16 {%0,%1,%2,%3}, [%4];\n"
                 : "=r"(r[0]), "=r"(r[1]), "=r"(r[2]), "=r"(r[3])
                 : "r"(addr) : "memory");
}
static __device__ __forceinline__ void ldsm2(unsigned* r, unsigned addr) {
    asm volatile("ldmatrix.sync.aligned.m8n8.x2.shared.b16 {%0,%1}, [%2];\n"
                 : "=r"(r[0]), "=r"(r[1])
                 : "r"(addr) : "memory");
}
static __device__ __forceinline__ void mma16816(float* c, const unsigned* a, const unsigned* b) {
    asm volatile("mma.sync.aligned.m16n8k16.row.col.f32.bf16.bf16.f32 "
                 "{%0,%1,%2,%3}, {%4,%5,%6,%7}, {%8,%9}, {%0,%1,%2,%3};\n"
                 : "+f"(c[0]), "+f"(c[1]), "+f"(c[2]), "+f"(c[3])
                 : "r"(a[0]), "r"(a[1]), "r"(a[2]), "r"(a[3]),
                   "r"(b[0]), "r"(b[1]));
}

__global__ __launch_bounds__(256, 1)
void entmax_attn_kernel(const float* __restrict__ Q, const float* __restrict__ K,
                        const float* __restrict__ V, float* __restrict__ O)
{
    extern __shared__ unsigned char smem[];
    float*    candS = (float*)(smem + OFF_CS);
    int*      candC = (int*)(smem + OFF_CC);
    unsigned* rowM  = (unsigned*)(smem + OFF_RM);
    int*      cnt   = (int*)(smem + OFF_CNT);
    float*    tauA  = (float*)(smem + OFF_TAU);
    float*    zA    = (float*)(smem + OFF_Z);

    const int tid  = threadIdx.x;
    const int lane = tid & 31;
    const int wid  = tid >> 5;
    const int b    = blockIdx.y;
    const int qt   = blockIdx.x;
    const int q0   = qt * BM;

    const float* Qb = Q + ((size_t)b * SEQ + q0) * DIM;
    const float* Kb = K + (size_t)b * SEQ * DIM;
    const float* Vb = V + (size_t)b * SEQ * DIM;
    const __nv_bfloat16* Qhb = g_Qh + ((size_t)b * SEQ + q0) * DIM;
    const __nv_bfloat16* Khb = g_Kh + (size_t)b * SEQ * DIM;

    const unsigned smemB = (unsigned)__cvta_generic_to_shared(smem);
    const unsigned qS = smemB + OFF_QHI;

    const int wm = wid & 1;          // 2 warps in M (64 rows each)
    const int wn = wid >> 1;         // 4 warps in N (32 cols each)
    const int g  = lane >> 2;
    const int t  = lane & 3;

    const int aRow = (lane & 7) + ((lane >> 3) & 1) * 8;
    const int aK   = ((lane >> 4) & 1) * 8;
    const int bRow = lane & 7;
    const int bK   = ((lane >> 3) & 1) * 8;

    if (tid < BM) { rowM[tid] = 0u; cnt[tid] = 0; }

    // fill chunk mapping: 2048 16B chunks per tile, 8 per thread
    const int frow0 = tid >> 4;        // rows tid/16 + 16*k
    const int fc16  = tid & 15;        // 16B column chunk

    // Q tile (group with tile 0)
    #pragma unroll
    for (int k = 0; k < 8; k++) {
        int r = frow0 + k * 16;
        cpasync16(qS + r * (QSTR * 2) + fc16 * 16, Qhb + r * DIM + fc16 * 8);
    }
    // K tile 0
    {
        const __nv_bfloat16* Kt = Khb;
        unsigned kD = smemB + OFF_KHI;
        #pragma unroll
        for (int k = 0; k < 8; k++) {
            int r = frow0 + k * 16;
            cpasync16(kD + r * (QSTR * 2) + fc16 * 16, Kt + r * DIM + fc16 * 8);
        }
    }
    cp_commit();
    // K tile 1
    {
        const __nv_bfloat16* Kt = Khb + (size_t)BN * DIM;
        unsigned kD = smemB + OFF_KHI + TILE_B;
        #pragma unroll
        for (int k = 0; k < 8; k++) {
            int r = frow0 + k * 16;
            cpasync16(kD + r * (QSTR * 2) + fc16 * 16, Kt + r * DIM + fc16 * 8);
        }
    }
    cp_commit();

    for (int nt = 0; nt < NT; nt++) {
        // issue tile nt+2 into stage (nt+2)%3
        if (nt + 2 < NT) {
            const __nv_bfloat16* Kt = Khb + (size_t)(nt + 2) * BN * DIM;
            unsigned kD = smemB + OFF_KHI + ((nt + 2) % STAGES) * TILE_B;
            #pragma unroll
            for (int k = 0; k < 8; k++) {
                int r = frow0 + k * 16;
                cpasync16(kD + r * (QSTR * 2) + fc16 * 16, Kt + r * DIM + fc16 * 8);
            }
            cp_commit();
        }
        // wait until tile nt is resident
        if (nt < NT - 2)      cp_wait<2>();
        else if (nt == NT - 2) cp_wait<1>();
        else                   cp_wait<0>();
        __syncthreads();

        const unsigned kS = smemB + OFF_KHI + (nt % STAGES) * TILE_B;

        float acc[4][4][4];
        #pragma unroll
        for (int m = 0; m < 4; m++)
            #pragma unroll
            for (int n = 0; n < 4; n++)
                #pragma unroll
                for (int e = 0; e < 4; e++) acc[m][n][e] = 0.f;

        #pragma unroll
        for (int ks = 0; ks < 8; ks++) {
            unsigned a[4][4], bb[4][2];
            #pragma unroll
            for (int m = 0; m < 4; m++)
                ldsm4(a[m], qS + (unsigned)(((wm * 64 + m * 16 + aRow) * QSTR + ks * 16 + aK) * 2));
            #pragma unroll
            for (int n = 0; n < 4; n++)
                ldsm2(bb[n], kS + (unsigned)(((wn * 32 + n * 8 + bRow) * QSTR + ks * 16 + bK) * 2));
            #pragma unroll
            for (int m = 0; m < 4; m++)
                #pragma unroll
                for (int n = 0; n < 4; n++)
                    mma16816(acc[m][n], a[m], bb[n]);
        }

        // per-row running max
        #pragma unroll
        for (int m = 0; m < 4; m++) {
            #pragma unroll
            for (int h = 0; h < 2; h++) {
                float lm = -3.0e38f;
                #pragma unroll
                for (int n = 0; n < 4; n++)
                    lm = fmaxf(lm, fmaxf(acc[m][n][h * 2], acc[m][n][h * 2 + 1]));
                lm = fmaxf(lm, __shfl_xor_sync(0xffffffffu, lm, 1));
                lm = fmaxf(lm, __shfl_xor_sync(0xffffffffu, lm, 2));
                if ((lane & 3) == 0)
                    atomicMax(&rowM[wm * 64 + m * 16 + h * 8 + g], fenc(lm));
            }
        }
        __syncthreads();

        // collect candidates: score > running rowmax - 3.5
        #pragma unroll
        for (int m = 0; m < 4; m++) {
            #pragma unroll
            for (int h = 0; h < 2; h++) {
                const int r = wm * 64 + m * 16 + h * 8 + g;
                const float thr = fdec(rowM[r]) - 3.5f;
                #pragma unroll
                for (int n = 0; n < 4; n++) {
                    #pragma unroll
                    for (int e = 0; e < 2; e++) {
                        float s = acc[m][n][h * 2 + e];
                        if (s > thr) {
                            int p = atomicAdd(&cnt[r], 1);
                            if (p < CAP) {
                                candS[r * CSTR + p] = s;
                                candC[r * CSTR + p] = nt * BN + wn * 32 + n * 8 + t * 2 + e;
                            }
                        }
                    }
                }
            }
        }
        __syncthreads();   // protect stage buffer reuse + rowM/cnt coherence
    }

    // ---- sort + exact fp32 rescore + bisection (lane-per-row, warps 0-3) ----
    if (wid < 4) {
        const int r = wid * 32 + lane;
        int c_ = cnt[r]; if (c_ > CAP) c_ = CAP;
        float* cs = candS + r * CSTR;
        int*   cc = candC + r * CSTR;

        for (int i = 1; i < c_; i++) {
            float sv = cs[i]; int kv = cc[i]; int j = i - 1;
            while (j >= 0 && cc[j] > kv) { cc[j + 1] = cc[j]; cs[j + 1] = cs[j]; j--; }
            cc[j + 1] = kv; cs[j + 1] = sv;
        }

        const float* qp = Qb + r * DIM;
        float smax = -3.0e38f;
        for (int j = 0; j < c_; j++) {
            const float* kp = Kb + (size_t)cc[j] * DIM;
            float s0 = 0.f, s1 = 0.f, s2 = 0.f, s3 = 0.f;
            #pragma unroll
            for (int d = 0; d < DIM / 4; d++) {
                float4 qv = *(const float4*)(qp + d * 4);
                float4 kv = *(const float4*)(kp + d * 4);
                s0 = fmaf(qv.x, kv.x, s0);
                s1 = fmaf(qv.y, kv.y, s1);
                s2 = fmaf(qv.z, kv.z, s2);
                s3 = fmaf(qv.w, kv.w, s3);
            }
            float s = (s0 + s1) + (s2 + s3);
            cs[j] = s;
            smax = fmaxf(smax, s);
        }

        const float zmax = 0.5f * smax;
        float tmin = zmax - 1.0f;
        float tmax = zmax - 0.022097086912079608f;   // float32(2048^-0.5)
        float tau = 0.5f * (tmin + tmax), Zv = 0.f;
        for (int it = 0; it < NITER; it++) {
            tau = 0.5f * (tmin + tmax);
            Zv = 0.f;
            for (int j = 0; j < c_; j++) {
                float dz = fmaxf(0.5f * cs[j] - tau, 0.f);
                Zv += dz * dz;
            }
            if (Zv >= 1.0f) tmin = tau; else tmax = tau;
        }
        tauA[r] = tau;
        zA[r]   = Zv;
    }
    __syncthreads();

    // ---- sparse P@V: warp per 16 rows, float4 coalesced V gather ----
    for (int rr = 0; rr < 16; rr++) {
        const int r = wid * 16 + rr;
        int c_ = cnt[r]; if (c_ > CAP) c_ = CAP;
        const float tau = tauA[r];
        const float Zv  = zA[r];
        float ax = 0.f, ay = 0.f, az = 0.f, aw = 0.f;
        for (int j = 0; j < c_; j++) {
            float dz = fmaxf(0.5f * candS[r * CSTR + j] - tau, 0.f);
            float w = (dz * dz) / Zv;
            const float4 v = *(const float4*)(Vb + (size_t)candC[r * CSTR + j] * DIM + lane * 4);
            ax = fmaf(w, v.x, ax);
            ay = fmaf(w, v.y, ay);
            az = fmaf(w, v.z, az);
            aw = fmaf(w, v.w, aw);
        }
        *(float4*)(O + ((size_t)b * SEQ + q0 + r) * DIM + lane * 4) = make_float4(ax, ay, az, aw);
    }
}

extern "C" void kernel_launch(void* const* d_in, const int* in_sizes, int n_in,
                              void* d_out, int out_size) {
    const float* Q = (const float*)d_in[0];
    const float* K = (const float*)d_in[1];
    const float* V = (const float*)d_in[2];
    float* O = (float*)d_out;

    cvt_kernel<<<2048, 256>>>(Q, K);

    cudaFuncSetAttribute(entmax_attn_kernel,
                         cudaFuncAttributeMaxDynamicSharedMemorySize, SMEM_BYTES);
    dim3 grid(QT, BATCH);
    entmax_attn_kernel<<<grid, 256, SMEM_BYTES>>>(Q, K, V, O);
}